// round 14
// baseline (speedup 1.0000x reference)
#include <cuda_runtime.h>
#include <cuda_fp16.h>
#include <cstdint>

#define HIDDEN   1024
#define HEADS    16
#define HEAD_DIM 64
#define BATCH    4
#define SEQ      2048
#define MROWS    (BATCH * SEQ)   /* 8192 */

// ---------------------------------------------------------------------------
// Device-global scratch
// ---------------------------------------------------------------------------
__device__ float  g_M [BATCH * HEADS * HEAD_DIM * HEAD_DIM];   // fp32 KtV accum

__device__ __half g_XHI[3ull * MROWS * HIDDEN];   // input X hi ([M][K])
__device__ __half g_WHI[3ull * HIDDEN * HIDDEN];  // W^T hi ([N][K])

__device__ __half g_YH[3ull * MROWS * HIDDEN];    // projected Q/K/V hi
__device__ __half g_YL[MROWS * HIDDEN];           // projected K lo (z==1 only)

// ---------------------------------------------------------------------------
// Helpers (target-portable sm_80-class PTX only)
// ---------------------------------------------------------------------------
__device__ __forceinline__ uint32_t smem_u32(const void* p) {
    uint32_t a;
    asm("{ .reg .u64 t; cvta.to.shared.u64 t, %1; cvt.u32.u64 %0, t; }" : "=r"(a) : "l"(p));
    return a;
}
__device__ __forceinline__ void cp16(uint32_t dst, const void* src) {
    asm volatile("cp.async.cg.shared.global [%0], [%1], 16;" :: "r"(dst), "l"(src));
}
#define CP_COMMIT() asm volatile("cp.async.commit_group;" ::: "memory")
#define CP_WAIT0()  asm volatile("cp.async.wait_group 0;"  ::: "memory")

__device__ __forceinline__ void ldsm4(uint32_t (&r)[4], uint32_t addr) {
    asm volatile("ldmatrix.sync.aligned.m8n8.x4.shared.b16 {%0,%1,%2,%3}, [%4];"
                 : "=r"(r[0]), "=r"(r[1]), "=r"(r[2]), "=r"(r[3]) : "r"(addr));
}
__device__ __forceinline__ void ldsm4t(uint32_t (&r)[4], uint32_t addr) {
    asm volatile("ldmatrix.sync.aligned.m8n8.x4.trans.shared.b16 {%0,%1,%2,%3}, [%4];"
                 : "=r"(r[0]), "=r"(r[1]), "=r"(r[2]), "=r"(r[3]) : "r"(addr));
}
__device__ __forceinline__ void mma_fp16(float (&c)[4], const uint32_t (&a)[4],
                                         uint32_t b0, uint32_t b1) {
    asm volatile("mma.sync.aligned.m16n8k16.row.col.f32.f16.f16.f32 "
                 "{%0,%1,%2,%3}, {%4,%5,%6,%7}, {%8,%9}, {%0,%1,%2,%3};"
                 : "+f"(c[0]), "+f"(c[1]), "+f"(c[2]), "+f"(c[3])
                 : "r"(a[0]), "r"(a[1]), "r"(a[2]), "r"(a[3]), "r"(b0), "r"(b1));
}

// ---------------------------------------------------------------------------
// Conversion kernels
// ---------------------------------------------------------------------------
struct Ptr3 { const float* p[3]; };

__global__ __launch_bounds__(256)
void split_x_kernel(Ptr3 in) {
    const int z = blockIdx.y;
    const size_t idx = ((size_t)blockIdx.x * blockDim.x + threadIdx.x) * 4;
    const float4 v = *reinterpret_cast<const float4*>(in.p[z] + idx);
    ushort4 hv = make_ushort4(__half_as_ushort(__float2half_rn(v.x)),
                              __half_as_ushort(__float2half_rn(v.y)),
                              __half_as_ushort(__float2half_rn(v.z)),
                              __half_as_ushort(__float2half_rn(v.w)));
    *reinterpret_cast<ushort4*>(g_XHI + (size_t)z * MROWS * HIDDEN + idx) = hv;
}

// W transpose+convert; blocks (z==0, y==0) additionally zero g_M.
__global__ __launch_bounds__(256)
void split_w_kernel(Ptr3 w) {
    __shared__ float t[32][33];
    const int z  = blockIdx.z;
    const int k0 = blockIdx.y * 32;
    const int n0 = blockIdx.x * 32;
    const int tx = threadIdx.x & 31;
    const int ty = threadIdx.x >> 5;
    const float* W = w.p[z];

    if (z == 0 && blockIdx.y == 0) {
        // 32 blocks x 256 threads zero 262144 floats (8 float4 each)
        const int gt = blockIdx.x * 256 + threadIdx.x;   // 0..8191
#pragma unroll
        for (int j = 0; j < 8; j++)
            *reinterpret_cast<float4*>(g_M + (size_t)(gt + j * 8192) * 4) =
                make_float4(0.f, 0.f, 0.f, 0.f);
    }

#pragma unroll
    for (int j = 0; j < 32; j += 8)
        t[ty + j][tx] = W[(size_t)(k0 + ty + j) * HIDDEN + n0 + tx];
    __syncthreads();

    __half* oh = g_WHI + (size_t)z * HIDDEN * HIDDEN;
#pragma unroll
    for (int j = 0; j < 32; j += 8)
        oh[(size_t)(n0 + ty + j) * HIDDEN + k0 + tx] = __float2half_rn(t[tx][ty + j]);
}

// ---------------------------------------------------------------------------
// fp16 1-term projection GEMM.  BM=64, BN=128, BK=64, 8 warps as 2(M)x4(N)
// (warp tile 32x32, acc=32 regs), 2-stage double buffer, 3 CTA/SM target,
// single sync per k-iter.  Epilogue writes Y-lo only for z==1 (K).
// ---------------------------------------------------------------------------
#define SSTR      144
#define A_ROWS    64
#define B_ROWS    128
#define A_BYTES   (A_ROWS * SSTR)        /* 9216  */
#define B_BYTES   (B_ROWS * SSTR)        /* 18432 */
#define OFF_A     0
#define OFF_B     (A_BYTES)
#define STAGE_B   (A_BYTES + B_BYTES)    /* 27648 */
#define SMEM_DYN  (2 * STAGE_B)          /* 55296 per CTA; 3 CTAs = 165888 */
#define KITERS    (HIDDEN / 64)          /* 16 */

struct GemmArgs { const float* Bv[3]; };

__device__ __forceinline__ void load_stage(uint32_t sbase,
                                           const __half* Ah, const __half* Bh, int tid) {
    // A: 64 rows x 8 chunks = 512 chunks -> 2/thread
#pragma unroll
    for (int j = 0; j < 2; j++) {
        const int c   = tid + j * 256;
        const int row = c >> 3;
        const int cc  = c & 7;
        cp16(sbase + OFF_A + (uint32_t)row * SSTR + (uint32_t)cc * 16,
             Ah + (size_t)row * HIDDEN + cc * 8);
    }
    // B: 128 rows x 8 chunks = 1024 chunks -> 4/thread
#pragma unroll
    for (int j = 0; j < 4; j++) {
        const int c   = tid + j * 256;
        const int row = c >> 3;
        const int cc  = c & 7;
        cp16(sbase + OFF_B + (uint32_t)row * SSTR + (uint32_t)cc * 16,
             Bh + (size_t)row * HIDDEN + cc * 8);
    }
}

__global__ __launch_bounds__(256, 3)
void proj_gemm_mma(GemmArgs args) {
    extern __shared__ char dynsmem[];
    const uint32_t sb0 = smem_u32(dynsmem);

    const int tid   = threadIdx.x;
    const int wid   = tid >> 5;
    const int lane  = tid & 31;
    const int warpM = wid & 1;          // 0..1  (32 rows each)
    const int warpN = wid >> 1;         // 0..3  (32 cols each)
    const int z     = blockIdx.z;
    const int n0    = blockIdx.x * 128;
    const int m0    = blockIdx.y * 64;

    const __half* Ah = g_XHI + (size_t)z * MROWS * HIDDEN + (size_t)m0 * HIDDEN;
    const __half* Bh = g_WHI + (size_t)z * HIDDEN * HIDDEN + (size_t)n0 * HIDDEN;

    const int grp = lane >> 3;
    const int rin = lane & 7;
    const uint32_t aBase = (uint32_t)(warpM * 32 + (grp & 1) * 8 + rin) * SSTR + (uint32_t)(grp >> 1) * 16;
    const uint32_t bBase = (uint32_t)(warpN * 32 + (grp >> 1) * 8 + rin) * SSTR + (uint32_t)(grp & 1) * 16;

    float acc[2][4][4];   // [mt][nt][reg] : 32 rows x 32 cols per warp
#pragma unroll
    for (int i = 0; i < 2; i++)
#pragma unroll
        for (int j = 0; j < 4; j++)
#pragma unroll
            for (int r = 0; r < 4; r++) acc[i][j][r] = 0.0f;

    load_stage(sb0, Ah, Bh, tid);
    CP_COMMIT();

    for (int i = 0; i < KITERS; i++) {
        const uint32_t sb = sb0 + (uint32_t)(i & 1) * STAGE_B;

        CP_WAIT0();                 // stage i complete
        __syncthreads();            // publish stage i; all warps past mma(i-1)
        if (i + 1 < KITERS) {
            const int ko = (i + 1) * 64;
            load_stage(sb0 + (uint32_t)((i + 1) & 1) * STAGE_B, Ah + ko, Bh + ko, tid);
            CP_COMMIT();
        }

#pragma unroll
        for (int ks = 0; ks < 4; ks++) {
            const uint32_t ksB = (uint32_t)ks * 32;
            uint32_t aH[2][4], bH[4][2];
#pragma unroll
            for (int mt = 0; mt < 2; mt++)
                ldsm4(aH[mt], sb + OFF_A + aBase + (uint32_t)mt * (16 * SSTR) + ksB);
#pragma unroll
            for (int p = 0; p < 2; p++) {
                uint32_t t[4];
                ldsm4(t, sb + OFF_B + bBase + (uint32_t)p * (16 * SSTR) + ksB);
                bH[2 * p][0] = t[0]; bH[2 * p][1] = t[1];
                bH[2 * p + 1][0] = t[2]; bH[2 * p + 1][1] = t[3];
            }
#pragma unroll
            for (int mt = 0; mt < 2; mt++)
#pragma unroll
                for (int nt = 0; nt < 4; nt++)
                    mma_fp16(acc[mt][nt], aH[mt], bH[nt][0], bH[nt][1]);
        }
    }

    // Epilogue: bias + fp16 hi (lo only for z==1, the K projection)
    const float* Bv = args.Bv[z];
    __half* YH = g_YH + (size_t)z * MROWS * HIDDEN;
    const bool wantLo = (z == 1);
    const int rowBase = m0 + warpM * 32 + (lane >> 2);
    const int colBase = n0 + warpN * 32 + (lane & 3) * 2;
#pragma unroll
    for (int mt = 0; mt < 2; mt++) {
#pragma unroll
        for (int nt = 0; nt < 4; nt++) {
            const int col = colBase + nt * 8;
            const float b0 = Bv[col], b1 = Bv[col + 1];
            const int r0 = rowBase + mt * 16;
#pragma unroll
            for (int rr = 0; rr < 2; rr++) {
                const float y0 = acc[mt][nt][rr * 2 + 0] + b0;
                const float y1 = acc[mt][nt][rr * 2 + 1] + b1;
                const __half h0 = __float2half_rn(y0);
                const __half h1 = __float2half_rn(y1);
                const size_t o = (size_t)(r0 + rr * 8) * HIDDEN + col;
                *reinterpret_cast<__half2*>(YH + o) = __halves2half2(h0, h1);
                if (wantLo) {
                    const __half l0 = __float2half_rn(y0 - __half2float(h0));
                    const __half l1 = __float2half_rn(y1 - __half2float(h1));
                    *reinterpret_cast<__half2*>(g_YL + o) = __halves2half2(l0, l1);
                }
            }
        }
    }
}

// ---------------------------------------------------------------------------
// ktv_tc: M_bh += K_bh^T V_bh  (2-term: Kh·Vh + Kl·Vh), single-sync pipeline.
// ---------------------------------------------------------------------------
#define KSS       144
#define KARR      (64 * KSS)
#define KOFF_KH   0
#define KOFF_KL   (KARR)
#define KOFF_VH   (2 * KARR)
#define KSTAGE    (3 * KARR)              /* 27648 */
#define KSMEM     (2 * KSTAGE)            /* 55296 */

__global__ __launch_bounds__(256)
void ktv_tc() {
    extern __shared__ char dynsmem[];
    const uint32_t sb0 = smem_u32(dynsmem);

    const int tid  = threadIdx.x;
    const int wid  = tid >> 5;
    const int lane = tid & 31;
    const int bh   = blockIdx.x;
    const int b    = bh >> 4;
    const int h    = bh & 15;
    const int sbeg = blockIdx.y * 512;

    const int quad = wid & 3;
    const int half = wid >> 2;
    const int mq   = (quad >> 1) * 32;
    const int nq   = (quad & 1) * 32;

    const size_t headoff = ((size_t)b * SEQ) * HIDDEN + h * HEAD_DIM;
    const __half* KH0 = g_YH + (size_t)1 * MROWS * HIDDEN + headoff;
    const __half* KL0 = g_YL + headoff;
    const __half* VH0 = g_YH + (size_t)2 * MROWS * HIDDEN + headoff;

    const int t  = lane >> 3;
    const int rr = lane & 7;
    const uint32_t aRow = (uint32_t)((t >> 1) * 8 + rr);
    const uint32_t aCol = (uint32_t)((t & 1) * 8);
    const uint32_t bRow = (uint32_t)((t & 1) * 8 + rr);
    const uint32_t bCol = (uint32_t)((t >> 1) * 8);

    float acc[2][4][4];
#pragma unroll
    for (int i = 0; i < 2; i++)
#pragma unroll
        for (int j = 0; j < 4; j++)
#pragma unroll
            for (int r = 0; r < 4; r++) acc[i][j][r] = 0.0f;

    auto load_chunk = [&](uint32_t sbase, int s0) {
#pragma unroll
        for (int j = 0; j < 2; j++) {
            const int c   = tid + j * 256;
            const int row = c >> 3;
            const int cc  = c & 7;
            const uint32_t d = sbase + (uint32_t)row * KSS + (uint32_t)cc * 16;
            const size_t   s = (size_t)(s0 + row) * HIDDEN + cc * 8;
            cp16(d + KOFF_KH, KH0 + s);
            cp16(d + KOFF_KL, KL0 + s);
            cp16(d + KOFF_VH, VH0 + s);
        }
    };

    load_chunk(sb0, sbeg);
    CP_COMMIT();

    for (int i = 0; i < 8; i++) {
        const uint32_t sb = sb0 + (uint32_t)(i & 1) * KSTAGE;
        CP_WAIT0();
        __syncthreads();
        if (i + 1 < 8) {
            load_chunk(sb0 + (uint32_t)((i + 1) & 1) * KSTAGE, sbeg + (i + 1) * 64);
            CP_COMMIT();
        }

        if (half == (i & 1)) {
#pragma unroll
            for (int kt = 0; kt < 4; kt++) {
                uint32_t ah[2][4], al[2][4], bh2[4][2];
#pragma unroll
                for (int mt = 0; mt < 2; mt++) {
                    const uint32_t ad = sb + (uint32_t)(kt * 16 + aRow) * KSS
                                      + (uint32_t)(mq + mt * 16 + aCol) * 2;
                    ldsm4t(ah[mt], ad + KOFF_KH);
                    ldsm4t(al[mt], ad + KOFF_KL);
                }
#pragma unroll
                for (int p = 0; p < 2; p++) {
                    const uint32_t bd = sb + (uint32_t)(kt * 16 + bRow) * KSS
                                      + (uint32_t)(nq + p * 16 + bCol) * 2;
                    uint32_t tt[4];
                    ldsm4t(tt, bd + KOFF_VH);
                    bh2[2 * p][0] = tt[0]; bh2[2 * p][1] = tt[1];
                    bh2[2 * p + 1][0] = tt[2]; bh2[2 * p + 1][1] = tt[3];
                }
#pragma unroll
                for (int mt = 0; mt < 2; mt++)
#pragma unroll
                    for (int nt = 0; nt < 4; nt++) {
                        mma_fp16(acc[mt][nt], ah[mt], bh2[nt][0], bh2[nt][1]);
                        mma_fp16(acc[mt][nt], al[mt], bh2[nt][0], bh2[nt][1]);
                    }
            }
        }
    }

    float* Mh = g_M + (size_t)bh * HEAD_DIM * HEAD_DIM;
#pragma unroll
    for (int mt = 0; mt < 2; mt++)
#pragma unroll
        for (int nt = 0; nt < 4; nt++) {
            const int row = mq + mt * 16 + (lane >> 2);
            const int col = nq + nt * 8 + (lane & 3) * 2;
            atomicAdd(&Mh[row * 64 + col],           acc[mt][nt][0]);
            atomicAdd(&Mh[row * 64 + col + 1],       acc[mt][nt][1]);
            atomicAdd(&Mh[(row + 8) * 64 + col],     acc[mt][nt][2]);
            atomicAdd(&Mh[(row + 8) * 64 + col + 1], acc[mt][nt][3]);
        }
}

// ---------------------------------------------------------------------------
// out_tc: out = scale * Q_bh @ M_bh  (2-term: Qh·Mh + Qh·Ml).
// Loads g_M fp32 and converts to hi/lo fp16 in smem (m_convert fused).
// ---------------------------------------------------------------------------
#define OOFF_QH   0
#define OOFF_MH   (128 * KSS)             /* 18432 */
#define OOFF_ML   (OOFF_MH + 64 * KSS)    /* 27648 */
#define OOFF_MF   (OOFF_ML + 64 * KSS)    /* 36864: fp32 staging 16KB */
#define OSMEM     (OOFF_MF + 64 * 64 * 4) /* 53248 */

__global__ __launch_bounds__(128)
void out_tc(float* __restrict__ out) {
    extern __shared__ char dynsmem[];
    const uint32_t sb = smem_u32(dynsmem);

    const int tid  = threadIdx.x;
    const int wid  = tid >> 5;
    const int lane = tid & 31;
    const int s0   = blockIdx.x * 128;
    const int bh   = blockIdx.y;
    const int b    = bh >> 4;
    const int h    = bh & 15;

    const size_t qoff = ((size_t)b * SEQ + s0) * HIDDEN + h * HEAD_DIM;
    const __half* QH0 = g_YH + qoff;          // z=0
    const float*  MF0 = g_M + (size_t)bh * HEAD_DIM * HEAD_DIM;

#pragma unroll
    for (int j = 0; j < 8; j++) {
        const int c   = tid + j * 128;
        const int row = c >> 3;
        const int cc  = c & 7;
        cp16(sb + OOFF_QH + (uint32_t)row * KSS + (uint32_t)cc * 16,
             QH0 + (size_t)row * HIDDEN + cc * 8);
    }
    // M fp32: 16KB = 1024 chunks of 16B -> 8/thread (contiguous staging)
#pragma unroll
    for (int j = 0; j < 8; j++) {
        const int c = tid + j * 128;
        cp16(sb + OOFF_MF + (uint32_t)c * 16, MF0 + c * 4);
    }
    CP_COMMIT();
    CP_WAIT0();
    __syncthreads();

    // Convert M fp32 -> hi/lo fp16 in smem
    const float* mf = reinterpret_cast<const float*>(dynsmem + OOFF_MF);
#pragma unroll
    for (int j = 0; j < 8; j++) {
        const int f4 = tid + j * 128;           // float4 index 0..1023
        const float4 v = reinterpret_cast<const float4*>(mf)[f4];
        const int f  = f4 * 4;
        const int row = f >> 6;
        const int col = f & 63;
        __half h0 = __float2half_rn(v.x), h1 = __float2half_rn(v.y);
        __half h2 = __float2half_rn(v.z), h3 = __float2half_rn(v.w);
        __half l0 = __float2half_rn(v.x - __half2float(h0));
        __half l1 = __float2half_rn(v.y - __half2float(h1));
        __half l2 = __float2half_rn(v.z - __half2float(h2));
        __half l3 = __float2half_rn(v.w - __half2float(h3));
        __half2* mh = reinterpret_cast<__half2*>(dynsmem + OOFF_MH + row * KSS + col * 2);
        __half2* ml = reinterpret_cast<__half2*>(dynsmem + OOFF_ML + row * KSS + col * 2);
        mh[0] = __halves2half2(h0, h1); mh[1] = __halves2half2(h2, h3);
        ml[0] = __halves2half2(l0, l1); ml[1] = __halves2half2(l2, l3);
    }
    __syncthreads();

    const int t  = lane >> 3;
    const int rr = lane & 7;
    const int mo = wid * 32;
    const uint32_t aRow = (uint32_t)((t & 1) * 8 + rr);
    const uint32_t aCol = (uint32_t)((t >> 1) * 8);
    const uint32_t bRow = (uint32_t)((t & 1) * 8 + rr);
    const uint32_t bCol = (uint32_t)((t >> 1) * 8);

    float acc[2][8][4];
#pragma unroll
    for (int i = 0; i < 2; i++)
#pragma unroll
        for (int j = 0; j < 8; j++)
#pragma unroll
            for (int r = 0; r < 4; r++) acc[i][j][r] = 0.0f;

#pragma unroll
    for (int kt = 0; kt < 4; kt++) {
        uint32_t ah[2][4], bh2[8][2], bl2[8][2];
#pragma unroll
        for (int mt = 0; mt < 2; mt++) {
            const uint32_t ad = sb + (uint32_t)(mo + mt * 16 + aRow) * KSS
                              + (uint32_t)(kt * 16 + aCol) * 2;
            ldsm4(ah[mt], ad + OOFF_QH);
        }
#pragma unroll
        for (int p = 0; p < 4; p++) {
            const uint32_t bd = sb + (uint32_t)(kt * 16 + bRow) * KSS
                              + (uint32_t)(p * 16 + bCol) * 2;
            uint32_t tt[4];
            ldsm4t(tt, bd + OOFF_MH);
            bh2[2 * p][0] = tt[0]; bh2[2 * p][1] = tt[1];
            bh2[2 * p + 1][0] = tt[2]; bh2[2 * p + 1][1] = tt[3];
            ldsm4t(tt, bd + OOFF_ML);
            bl2[2 * p][0] = tt[0]; bl2[2 * p][1] = tt[1];
            bl2[2 * p + 1][0] = tt[2]; bl2[2 * p + 1][1] = tt[3];
        }
#pragma unroll
        for (int mt = 0; mt < 2; mt++)
#pragma unroll
            for (int nt = 0; nt < 8; nt++) {
                mma_fp16(acc[mt][nt], ah[mt], bh2[nt][0], bh2[nt][1]);
                mma_fp16(acc[mt][nt], ah[mt], bl2[nt][0], bl2[nt][1]);
            }
    }

    const float scale = 0.125f;
#pragma unroll
    for (int mt = 0; mt < 2; mt++)
#pragma unroll
        for (int nt = 0; nt < 8; nt++) {
            const int row = s0 + mo + mt * 16 + (lane >> 2);
            const int col = nt * 8 + (lane & 3) * 2;
            float* o0 = out + ((size_t)b * SEQ + row) * HIDDEN + h * HEAD_DIM + col;
            *reinterpret_cast<float2*>(o0) =
                make_float2(scale * acc[mt][nt][0], scale * acc[mt][nt][1]);
            *reinterpret_cast<float2*>(o0 + 8 * HIDDEN) =
                make_float2(scale * acc[mt][nt][2], scale * acc[mt][nt][3]);
        }
}

// ---------------------------------------------------------------------------
extern "C" void kernel_launch(void* const* d_in, const int* in_sizes, int n_in,
                              void* d_out, int out_size) {
    (void)in_sizes; (void)n_in; (void)out_size;
    const float* query = (const float*)d_in[0];
    const float* key   = (const float*)d_in[1];
    const float* value = (const float*)d_in[2];
    const float* q_w   = (const float*)d_in[3];
    const float* q_b   = (const float*)d_in[4];
    const float* k_w   = (const float*)d_in[5];
    const float* k_b   = (const float*)d_in[6];
    const float* v_w   = (const float*)d_in[7];
    const float* v_b   = (const float*)d_in[8];
    float* out = (float*)d_out;

    cudaFuncSetAttribute(proj_gemm_mma, cudaFuncAttributeMaxDynamicSharedMemorySize, SMEM_DYN);
    cudaFuncSetAttribute(ktv_tc, cudaFuncAttributeMaxDynamicSharedMemorySize, KSMEM);
    cudaFuncSetAttribute(out_tc, cudaFuncAttributeMaxDynamicSharedMemorySize, OSMEM);

    Ptr3 xin; xin.p[0] = query; xin.p[1] = key; xin.p[2] = value;
    Ptr3 win; win.p[0] = q_w;   win.p[1] = k_w; win.p[2] = v_w;

    // 1. fp32 -> fp16 conversions (split_w also zeros g_M)
    dim3 xgrid((unsigned)((size_t)MROWS * HIDDEN / 4 / 256), 3);
    split_x_kernel<<<xgrid, 256>>>(xin);
    split_w_kernel<<<dim3(HIDDEN / 32, HIDDEN / 32, 3), 256>>>(win);

    // 2. Tensor-core projections (1-term fp16, BM=64, 3 CTA/SM)
    GemmArgs ga;
    ga.Bv[0] = q_b; ga.Bv[1] = k_b; ga.Bv[2] = v_b;
    proj_gemm_mma<<<dim3(HIDDEN / 128, MROWS / 64, 3), 256, SMEM_DYN>>>(ga);

    // 3. Tensor-core K^T V (2-term, split-4 over S, fp32 atomic accum)
    ktv_tc<<<dim3(BATCH * HEADS, 4), 256, KSMEM>>>();

    // 4. Tensor-core Q @ M (2-term, fused M conversion) -> out
    out_tc<<<dim3(SEQ / 128, BATCH * HEADS), 128, OSMEM>>>(out);
}

// round 15
// speedup vs baseline: 1.0849x; 1.0849x over previous
#include <cuda_runtime.h>
#include <cuda_fp16.h>
#include <cstdint>

#define HIDDEN   1024
#define HEADS    16
#define HEAD_DIM 64
#define BATCH    4
#define SEQ      2048
#define MROWS    (BATCH * SEQ)   /* 8192 */

// ---------------------------------------------------------------------------
// Device-global scratch
// ---------------------------------------------------------------------------
__device__ float  g_M [BATCH * HEADS * HEAD_DIM * HEAD_DIM];   // fp32 KtV accum

__device__ __half g_XHI[3ull * MROWS * HIDDEN];   // input X hi ([M][K])
__device__ __half g_WHI[3ull * HIDDEN * HIDDEN];  // W^T hi ([N][K])

__device__ __half g_YH[3ull * MROWS * HIDDEN];    // projected Q/K/V (fp16)

// ---------------------------------------------------------------------------
// Helpers (target-portable sm_80-class PTX only)
// ---------------------------------------------------------------------------
__device__ __forceinline__ uint32_t smem_u32(const void* p) {
    uint32_t a;
    asm("{ .reg .u64 t; cvta.to.shared.u64 t, %1; cvt.u32.u64 %0, t; }" : "=r"(a) : "l"(p));
    return a;
}
__device__ __forceinline__ void cp16(uint32_t dst, const void* src) {
    asm volatile("cp.async.cg.shared.global [%0], [%1], 16;" :: "r"(dst), "l"(src));
}
#define CP_COMMIT() asm volatile("cp.async.commit_group;" ::: "memory")
#define CP_WAIT0()  asm volatile("cp.async.wait_group 0;"  ::: "memory")

__device__ __forceinline__ void ldsm4(uint32_t (&r)[4], uint32_t addr) {
    asm volatile("ldmatrix.sync.aligned.m8n8.x4.shared.b16 {%0,%1,%2,%3}, [%4];"
                 : "=r"(r[0]), "=r"(r[1]), "=r"(r[2]), "=r"(r[3]) : "r"(addr));
}
__device__ __forceinline__ void ldsm4t(uint32_t (&r)[4], uint32_t addr) {
    asm volatile("ldmatrix.sync.aligned.m8n8.x4.trans.shared.b16 {%0,%1,%2,%3}, [%4];"
                 : "=r"(r[0]), "=r"(r[1]), "=r"(r[2]), "=r"(r[3]) : "r"(addr));
}
__device__ __forceinline__ void mma_fp16(float (&c)[4], const uint32_t (&a)[4],
                                         uint32_t b0, uint32_t b1) {
    asm volatile("mma.sync.aligned.m16n8k16.row.col.f32.f16.f16.f32 "
                 "{%0,%1,%2,%3}, {%4,%5,%6,%7}, {%8,%9}, {%0,%1,%2,%3};"
                 : "+f"(c[0]), "+f"(c[1]), "+f"(c[2]), "+f"(c[3])
                 : "r"(a[0]), "r"(a[1]), "r"(a[2]), "r"(a[3]), "r"(b0), "r"(b1));
}

// ---------------------------------------------------------------------------
// Conversion kernels
// ---------------------------------------------------------------------------
struct Ptr3 { const float* p[3]; };

__global__ __launch_bounds__(256)
void split_x_kernel(Ptr3 in) {
    const int z = blockIdx.y;
    const size_t idx = ((size_t)blockIdx.x * blockDim.x + threadIdx.x) * 4;
    const float4 v = *reinterpret_cast<const float4*>(in.p[z] + idx);
    ushort4 hv = make_ushort4(__half_as_ushort(__float2half_rn(v.x)),
                              __half_as_ushort(__float2half_rn(v.y)),
                              __half_as_ushort(__float2half_rn(v.z)),
                              __half_as_ushort(__float2half_rn(v.w)));
    *reinterpret_cast<ushort4*>(g_XHI + (size_t)z * MROWS * HIDDEN + idx) = hv;
}

// W transpose+convert; blocks (z==0, y==0) additionally zero g_M.
__global__ __launch_bounds__(256)
void split_w_kernel(Ptr3 w) {
    __shared__ float t[32][33];
    const int z  = blockIdx.z;
    const int k0 = blockIdx.y * 32;
    const int n0 = blockIdx.x * 32;
    const int tx = threadIdx.x & 31;
    const int ty = threadIdx.x >> 5;
    const float* W = w.p[z];

    if (z == 0 && blockIdx.y == 0) {
        const int gt = blockIdx.x * 256 + threadIdx.x;   // 0..8191
#pragma unroll
        for (int j = 0; j < 8; j++)
            *reinterpret_cast<float4*>(g_M + (size_t)(gt + j * 8192) * 4) =
                make_float4(0.f, 0.f, 0.f, 0.f);
    }

#pragma unroll
    for (int j = 0; j < 32; j += 8)
        t[ty + j][tx] = W[(size_t)(k0 + ty + j) * HIDDEN + n0 + tx];
    __syncthreads();

    __half* oh = g_WHI + (size_t)z * HIDDEN * HIDDEN;
#pragma unroll
    for (int j = 0; j < 32; j += 8)
        oh[(size_t)(n0 + ty + j) * HIDDEN + k0 + tx] = __float2half_rn(t[tx][ty + j]);
}

// ---------------------------------------------------------------------------
// fp16 1-term projection GEMM (R13 winner config).  BM=128, BN=128, BK=64,
// 8 warps as 4(M)x2(N) (warp tile 32x64), 2-stage double buffer, 2 CTA/SM,
// single sync per k-iter.  Epilogue: bias + fp16 hi only.
// ---------------------------------------------------------------------------
#define SSTR      144
#define A_BYTES   (128 * SSTR)           /* 18432 */
#define OFF_A     0
#define OFF_B     (A_BYTES)
#define STAGE_B   (2 * A_BYTES)          /* 36864 */
#define SMEM_DYN  (2 * STAGE_B)          /* 73728 per CTA */
#define KITERS    (HIDDEN / 64)          /* 16 */

struct GemmArgs { const float* Bv[3]; };

__device__ __forceinline__ void load_stage(uint32_t sbase,
                                           const __half* Ah, const __half* Bh, int tid) {
#pragma unroll
    for (int j = 0; j < 4; j++) {
        const int c   = tid + j * 256;
        const int row = c >> 3;
        const int cc  = c & 7;
        const uint32_t d = sbase + (uint32_t)row * SSTR + (uint32_t)cc * 16;
        const size_t   s = (size_t)row * HIDDEN + cc * 8;
        cp16(d + OFF_A, Ah + s);
        cp16(d + OFF_B, Bh + s);
    }
}

__global__ __launch_bounds__(256, 2)
void proj_gemm_mma(GemmArgs args) {
    extern __shared__ char dynsmem[];
    const uint32_t sb0 = smem_u32(dynsmem);

    const int tid   = threadIdx.x;
    const int wid   = tid >> 5;
    const int lane  = tid & 31;
    const int warpM = wid & 3;          // 0..3  (32 rows each)
    const int warpN = wid >> 2;         // 0..1  (64 cols each)
    const int z     = blockIdx.z;
    const int n0    = blockIdx.x * 128;
    const int m0    = blockIdx.y * 128;

    const __half* Ah = g_XHI + (size_t)z * MROWS * HIDDEN + (size_t)m0 * HIDDEN;
    const __half* Bh = g_WHI + (size_t)z * HIDDEN * HIDDEN + (size_t)n0 * HIDDEN;

    const int grp = lane >> 3;
    const int rin = lane & 7;
    const uint32_t aBase = (uint32_t)(warpM * 32 + (grp & 1) * 8 + rin) * SSTR + (uint32_t)(grp >> 1) * 16;
    const uint32_t bBase = (uint32_t)(warpN * 64 + (grp >> 1) * 8 + rin) * SSTR + (uint32_t)(grp & 1) * 16;

    float acc[2][8][4];   // [mt][nt][reg] : 32 rows x 64 cols per warp
#pragma unroll
    for (int i = 0; i < 2; i++)
#pragma unroll
        for (int j = 0; j < 8; j++)
#pragma unroll
            for (int r = 0; r < 4; r++) acc[i][j][r] = 0.0f;

    load_stage(sb0, Ah, Bh, tid);
    CP_COMMIT();

    for (int i = 0; i < KITERS; i++) {
        const uint32_t sb = sb0 + (uint32_t)(i & 1) * STAGE_B;

        CP_WAIT0();                 // stage i complete
        __syncthreads();            // publish stage i; all warps past mma(i-1)
        if (i + 1 < KITERS) {
            const int ko = (i + 1) * 64;
            load_stage(sb0 + (uint32_t)((i + 1) & 1) * STAGE_B, Ah + ko, Bh + ko, tid);
            CP_COMMIT();
        }

#pragma unroll
        for (int ks = 0; ks < 4; ks++) {
            const uint32_t ksB = (uint32_t)ks * 32;
            uint32_t aH[2][4], bH[8][2];
#pragma unroll
            for (int mt = 0; mt < 2; mt++)
                ldsm4(aH[mt], sb + OFF_A + aBase + (uint32_t)mt * (16 * SSTR) + ksB);
#pragma unroll
            for (int p = 0; p < 4; p++) {
                uint32_t t[4];
                ldsm4(t, sb + OFF_B + bBase + (uint32_t)p * (16 * SSTR) + ksB);
                bH[2 * p][0] = t[0]; bH[2 * p][1] = t[1];
                bH[2 * p + 1][0] = t[2]; bH[2 * p + 1][1] = t[3];
            }
#pragma unroll
            for (int mt = 0; mt < 2; mt++)
#pragma unroll
                for (int nt = 0; nt < 8; nt++)
                    mma_fp16(acc[mt][nt], aH[mt], bH[nt][0], bH[nt][1]);
        }
    }

    // Epilogue: bias + fp16 hi
    const float* Bv = args.Bv[z];
    __half* YH = g_YH + (size_t)z * MROWS * HIDDEN;
    const int rowBase = m0 + warpM * 32 + (lane >> 2);
    const int colBase = n0 + warpN * 64 + (lane & 3) * 2;
#pragma unroll
    for (int mt = 0; mt < 2; mt++) {
#pragma unroll
        for (int nt = 0; nt < 8; nt++) {
            const int col = colBase + nt * 8;
            const float b0 = Bv[col], b1 = Bv[col + 1];
            const int r0 = rowBase + mt * 16;
#pragma unroll
            for (int rr = 0; rr < 2; rr++) {
                const float y0 = acc[mt][nt][rr * 2 + 0] + b0;
                const float y1 = acc[mt][nt][rr * 2 + 1] + b1;
                const size_t o = (size_t)(r0 + rr * 8) * HIDDEN + col;
                *reinterpret_cast<__half2*>(YH + o) =
                    __halves2half2(__float2half_rn(y0), __float2half_rn(y1));
            }
        }
    }
}

// ---------------------------------------------------------------------------
// ktv_tc: M_bh += K_bh^T V_bh  (1-term: Kh·Vh), single-sync pipeline.
// DRAM-bound: reads KH + VH (32 MB total).
// ---------------------------------------------------------------------------
#define KSS       144
#define KARR      (64 * KSS)
#define KOFF_KH   0
#define KOFF_VH   (KARR)
#define KSTAGE    (2 * KARR)              /* 18432 */
#define KSMEM     (2 * KSTAGE)            /* 36864 */

__global__ __launch_bounds__(256)
void ktv_tc() {
    extern __shared__ char dynsmem[];
    const uint32_t sb0 = smem_u32(dynsmem);

    const int tid  = threadIdx.x;
    const int wid  = tid >> 5;
    const int lane = tid & 31;
    const int bh   = blockIdx.x;
    const int b    = bh >> 4;
    const int h    = bh & 15;
    const int sbeg = blockIdx.y * 512;

    const int quad = wid & 3;
    const int half = wid >> 2;
    const int mq   = (quad >> 1) * 32;
    const int nq   = (quad & 1) * 32;

    const size_t headoff = ((size_t)b * SEQ) * HIDDEN + h * HEAD_DIM;
    const __half* KH0 = g_YH + (size_t)1 * MROWS * HIDDEN + headoff;
    const __half* VH0 = g_YH + (size_t)2 * MROWS * HIDDEN + headoff;

    const int t  = lane >> 3;
    const int rr = lane & 7;
    const uint32_t aRow = (uint32_t)((t >> 1) * 8 + rr);
    const uint32_t aCol = (uint32_t)((t & 1) * 8);
    const uint32_t bRow = (uint32_t)((t & 1) * 8 + rr);
    const uint32_t bCol = (uint32_t)((t >> 1) * 8);

    float acc[2][4][4];
#pragma unroll
    for (int i = 0; i < 2; i++)
#pragma unroll
        for (int j = 0; j < 4; j++)
#pragma unroll
            for (int r = 0; r < 4; r++) acc[i][j][r] = 0.0f;

    auto load_chunk = [&](uint32_t sbase, int s0) {
#pragma unroll
        for (int j = 0; j < 2; j++) {
            const int c   = tid + j * 256;
            const int row = c >> 3;
            const int cc  = c & 7;
            const uint32_t d = sbase + (uint32_t)row * KSS + (uint32_t)cc * 16;
            const size_t   s = (size_t)(s0 + row) * HIDDEN + cc * 8;
            cp16(d + KOFF_KH, KH0 + s);
            cp16(d + KOFF_VH, VH0 + s);
        }
    };

    load_chunk(sb0, sbeg);
    CP_COMMIT();

    for (int i = 0; i < 8; i++) {
        const uint32_t sb = sb0 + (uint32_t)(i & 1) * KSTAGE;
        CP_WAIT0();
        __syncthreads();
        if (i + 1 < 8) {
            load_chunk(sb0 + (uint32_t)((i + 1) & 1) * KSTAGE, sbeg + (i + 1) * 64);
            CP_COMMIT();
        }

        if (half == (i & 1)) {
#pragma unroll
            for (int kt = 0; kt < 4; kt++) {
                uint32_t ah[2][4], bh2[4][2];
#pragma unroll
                for (int mt = 0; mt < 2; mt++) {
                    const uint32_t ad = sb + (uint32_t)(kt * 16 + aRow) * KSS
                                      + (uint32_t)(mq + mt * 16 + aCol) * 2;
                    ldsm4t(ah[mt], ad + KOFF_KH);
                }
#pragma unroll
                for (int p = 0; p < 2; p++) {
                    const uint32_t bd = sb + (uint32_t)(kt * 16 + bRow) * KSS
                                      + (uint32_t)(nq + p * 16 + bCol) * 2;
                    uint32_t tt[4];
                    ldsm4t(tt, bd + KOFF_VH);
                    bh2[2 * p][0] = tt[0]; bh2[2 * p][1] = tt[1];
                    bh2[2 * p + 1][0] = tt[2]; bh2[2 * p + 1][1] = tt[3];
                }
#pragma unroll
                for (int mt = 0; mt < 2; mt++)
#pragma unroll
                    for (int nt = 0; nt < 4; nt++)
                        mma_fp16(acc[mt][nt], ah[mt], bh2[nt][0], bh2[nt][1]);
            }
        }
    }

    float* Mh = g_M + (size_t)bh * HEAD_DIM * HEAD_DIM;
#pragma unroll
    for (int mt = 0; mt < 2; mt++)
#pragma unroll
        for (int nt = 0; nt < 4; nt++) {
            const int row = mq + mt * 16 + (lane >> 2);
            const int col = nq + nt * 8 + (lane & 3) * 2;
            atomicAdd(&Mh[row * 64 + col],           acc[mt][nt][0]);
            atomicAdd(&Mh[row * 64 + col + 1],       acc[mt][nt][1]);
            atomicAdd(&Mh[(row + 8) * 64 + col],     acc[mt][nt][2]);
            atomicAdd(&Mh[(row + 8) * 64 + col + 1], acc[mt][nt][3]);
        }
}

// ---------------------------------------------------------------------------
// out_tc: out = scale * Q_bh @ M_bh  (2-term: Qh·Mh + Qh·Ml).
// Loads g_M fp32 and converts to hi/lo fp16 in smem (m_convert fused).
// ---------------------------------------------------------------------------
#define OOFF_QH   0
#define OOFF_MH   (128 * KSS)             /* 18432 */
#define OOFF_ML   (OOFF_MH + 64 * KSS)    /* 27648 */
#define OOFF_MF   (OOFF_ML + 64 * KSS)    /* 36864: fp32 staging 16KB */
#define OSMEM     (OOFF_MF + 64 * 64 * 4) /* 53248 */

__global__ __launch_bounds__(128)
void out_tc(float* __restrict__ out) {
    extern __shared__ char dynsmem[];
    const uint32_t sb = smem_u32(dynsmem);

    const int tid  = threadIdx.x;
    const int wid  = tid >> 5;
    const int lane = tid & 31;
    const int s0   = blockIdx.x * 128;
    const int bh   = blockIdx.y;
    const int b    = bh >> 4;
    const int h    = bh & 15;

    const size_t qoff = ((size_t)b * SEQ + s0) * HIDDEN + h * HEAD_DIM;
    const __half* QH0 = g_YH + qoff;          // z=0
    const float*  MF0 = g_M + (size_t)bh * HEAD_DIM * HEAD_DIM;

#pragma unroll
    for (int j = 0; j < 8; j++) {
        const int c   = tid + j * 128;
        const int row = c >> 3;
        const int cc  = c & 7;
        cp16(sb + OOFF_QH + (uint32_t)row * KSS + (uint32_t)cc * 16,
             QH0 + (size_t)row * HIDDEN + cc * 8);
    }
#pragma unroll
    for (int j = 0; j < 8; j++) {
        const int c = tid + j * 128;
        cp16(sb + OOFF_MF + (uint32_t)c * 16, MF0 + c * 4);
    }
    CP_COMMIT();
    CP_WAIT0();
    __syncthreads();

    // Convert M fp32 -> hi/lo fp16 in smem
    const float* mf = reinterpret_cast<const float*>(dynsmem + OOFF_MF);
#pragma unroll
    for (int j = 0; j < 8; j++) {
        const int f4 = tid + j * 128;
        const float4 v = reinterpret_cast<const float4*>(mf)[f4];
        const int f  = f4 * 4;
        const int row = f >> 6;
        const int col = f & 63;
        __half h0 = __float2half_rn(v.x), h1 = __float2half_rn(v.y);
        __half h2 = __float2half_rn(v.z), h3 = __float2half_rn(v.w);
        __half l0 = __float2half_rn(v.x - __half2float(h0));
        __half l1 = __float2half_rn(v.y - __half2float(h1));
        __half l2 = __float2half_rn(v.z - __half2float(h2));
        __half l3 = __float2half_rn(v.w - __half2float(h3));
        __half2* mh = reinterpret_cast<__half2*>(dynsmem + OOFF_MH + row * KSS + col * 2);
        __half2* ml = reinterpret_cast<__half2*>(dynsmem + OOFF_ML + row * KSS + col * 2);
        mh[0] = __halves2half2(h0, h1); mh[1] = __halves2half2(h2, h3);
        ml[0] = __halves2half2(l0, l1); ml[1] = __halves2half2(l2, l3);
    }
    __syncthreads();

    const int t  = lane >> 3;
    const int rr = lane & 7;
    const int mo = wid * 32;
    const uint32_t aRow = (uint32_t)((t & 1) * 8 + rr);
    const uint32_t aCol = (uint32_t)((t >> 1) * 8);
    const uint32_t bRow = (uint32_t)((t & 1) * 8 + rr);
    const uint32_t bCol = (uint32_t)((t >> 1) * 8);

    float acc[2][8][4];
#pragma unroll
    for (int i = 0; i < 2; i++)
#pragma unroll
        for (int j = 0; j < 8; j++)
#pragma unroll
            for (int r = 0; r < 4; r++) acc[i][j][r] = 0.0f;

#pragma unroll
    for (int kt = 0; kt < 4; kt++) {
        uint32_t ah[2][4], bh2[8][2], bl2[8][2];
#pragma unroll
        for (int mt = 0; mt < 2; mt++) {
            const uint32_t ad = sb + (uint32_t)(mo + mt * 16 + aRow) * KSS
                              + (uint32_t)(kt * 16 + aCol) * 2;
            ldsm4(ah[mt], ad + OOFF_QH);
        }
#pragma unroll
        for (int p = 0; p < 4; p++) {
            const uint32_t bd = sb + (uint32_t)(kt * 16 + bRow) * KSS
                              + (uint32_t)(p * 16 + bCol) * 2;
            uint32_t tt[4];
            ldsm4t(tt, bd + OOFF_MH);
            bh2[2 * p][0] = tt[0]; bh2[2 * p][1] = tt[1];
            bh2[2 * p + 1][0] = tt[2]; bh2[2 * p + 1][1] = tt[3];
            ldsm4t(tt, bd + OOFF_ML);
            bl2[2 * p][0] = tt[0]; bl2[2 * p][1] = tt[1];
            bl2[2 * p + 1][0] = tt[2]; bl2[2 * p + 1][1] = tt[3];
        }
#pragma unroll
        for (int mt = 0; mt < 2; mt++)
#pragma unroll
            for (int nt = 0; nt < 8; nt++) {
                mma_fp16(acc[mt][nt], ah[mt], bh2[nt][0], bh2[nt][1]);
                mma_fp16(acc[mt][nt], ah[mt], bl2[nt][0], bl2[nt][1]);
            }
    }

    const float scale = 0.125f;
#pragma unroll
    for (int mt = 0; mt < 2; mt++)
#pragma unroll
        for (int nt = 0; nt < 8; nt++) {
            const int row = s0 + mo + mt * 16 + (lane >> 2);
            const int col = nt * 8 + (lane & 3) * 2;
            float* o0 = out + ((size_t)b * SEQ + row) * HIDDEN + h * HEAD_DIM + col;
            *reinterpret_cast<float2*>(o0) =
                make_float2(scale * acc[mt][nt][0], scale * acc[mt][nt][1]);
            *reinterpret_cast<float2*>(o0 + 8 * HIDDEN) =
                make_float2(scale * acc[mt][nt][2], scale * acc[mt][nt][3]);
        }
}

// ---------------------------------------------------------------------------
extern "C" void kernel_launch(void* const* d_in, const int* in_sizes, int n_in,
                              void* d_out, int out_size) {
    (void)in_sizes; (void)n_in; (void)out_size;
    const float* query = (const float*)d_in[0];
    const float* key   = (const float*)d_in[1];
    const float* value = (const float*)d_in[2];
    const float* q_w   = (const float*)d_in[3];
    const float* q_b   = (const float*)d_in[4];
    const float* k_w   = (const float*)d_in[5];
    const float* k_b   = (const float*)d_in[6];
    const float* v_w   = (const float*)d_in[7];
    const float* v_b   = (const float*)d_in[8];
    float* out = (float*)d_out;

    cudaFuncSetAttribute(proj_gemm_mma, cudaFuncAttributeMaxDynamicSharedMemorySize, SMEM_DYN);
    cudaFuncSetAttribute(ktv_tc, cudaFuncAttributeMaxDynamicSharedMemorySize, KSMEM);
    cudaFuncSetAttribute(out_tc, cudaFuncAttributeMaxDynamicSharedMemorySize, OSMEM);

    Ptr3 xin; xin.p[0] = query; xin.p[1] = key; xin.p[2] = value;
    Ptr3 win; win.p[0] = q_w;   win.p[1] = k_w; win.p[2] = v_w;

    // 1. fp32 -> fp16 conversions (split_w also zeros g_M)
    dim3 xgrid((unsigned)((size_t)MROWS * HIDDEN / 4 / 256), 3);
    split_x_kernel<<<xgrid, 256>>>(xin);
    split_w_kernel<<<dim3(HIDDEN / 32, HIDDEN / 32, 3), 256>>>(win);

    // 2. Tensor-core projections (1-term fp16, R13 config)
    GemmArgs ga;
    ga.Bv[0] = q_b; ga.Bv[1] = k_b; ga.Bv[2] = v_b;
    proj_gemm_mma<<<dim3(HIDDEN / 128, MROWS / 128, 3), 256, SMEM_DYN>>>(ga);

    // 3. Tensor-core K^T V (1-term, split-4 over S, fp32 atomic accum)
    ktv_tc<<<dim3(BATCH * HEADS, 4), 256, KSMEM>>>();

    // 4. Tensor-core Q @ M (2-term, fused M conversion) -> out
    out_tc<<<dim3(SEQ / 128, BATCH * HEADS), 128, OSMEM>>>(out);
}